// round 6
// baseline (speedup 1.0000x reference)
#include <cuda_runtime.h>

typedef unsigned long long u64;

#define NP 64
#define NCOLS 500000
#define BCOLS 256
#define NB    ((NCOLS + BCOLS - 1) / BCOLS)   /* 1954 */
#define NANG 2016
#define KCH   8                               /* K rows per staged chunk */
#define NCH   (NP / KCH)                      /* 8 chunks */
#define NBUF  4                               /* smem ring depth */

// RT[r*64 + i] = mus[i] * R[i][r]
__device__ float d_RT[NP * NP];

// ---------------------------------------------------------------------------
// Kernel 1: build 64x64 combined rotation+scale matrix.
// Thread j owns column j (stride-64 smem, conflict-free). Sweeps padded to
// multiples of 8 with identity rotations (c=1,s=0) from a per-sweep padded
// cs table. Chunk-of-8 software pipeline: next chunk's mb/(c,s) prefetched and
// s*mb, c*mb precomputed off-chain; the vt chain is 1 FFMA (4 cyc)/rotation.
// ---------------------------------------------------------------------------
#define MROWS 80   /* 64 real + pad rows (max ib = 70) */

__global__ void __launch_bounds__(64)
build_R_kernel(const float* __restrict__ angles, const float* __restrict__ mus) {
    __shared__ float2 cs[63 * 64];        // per-sweep padded, identity elsewhere
    __shared__ float  M[MROWS * NP];
    const int j = threadIdx.x;

    // identity-init cs: slot it*64+j is written only by thread j in both phases
    for (int it = 0; it < 63; it++) cs[it * 64 + j] = make_float2(1.f, 0.f);
    {   // scatter real (c,s): sweep it has n = 63-it angles at base
        int base = 0;
        for (int it = 0; it < 63; it++) {
            const int n = 63 - it;
            if (j < n) {
                float s, c;
                sincosf(angles[base + j], &s, &c);
                cs[it * 64 + j] = make_float2(c, s);
            }
            base += n;
        }
    }
    #pragma unroll
    for (int i = 0; i < MROWS; i++) M[i * NP + j] = (i == j) ? 1.0f : 0.0f;
    __syncthreads();

    for (int it = 0; it < 63; it++) {
        const int n8 = (63 - it + 7) & ~7;     // padded rotation count
        float* bb = &M[(it + 1) * NP + j];     // vb rows base (stride 64)
        const float2* csrow = &cs[it * 64];

        float vt = M[it * NP + j];
        float  mbn[8];
        float2 ccn[8];
        #pragma unroll
        for (int r = 0; r < 8; r++) { mbn[r] = bb[r * NP]; ccn[r] = csrow[r]; }

        for (int c8 = 0; c8 < n8; c8 += 8) {
            float csx[8], csy[8], smb[8], cmb[8];
            #pragma unroll
            for (int r = 0; r < 8; r++) {
                csx[r] = ccn[r].x;  csy[r] = ccn[r].y;
                smb[r] = csy[r] * mbn[r];
                cmb[r] = csx[r] * mbn[r];
            }
            if (c8 + 8 < n8) {
                #pragma unroll
                for (int r = 0; r < 8; r++) {
                    mbn[r] = bb[(c8 + 8 + r) * NP];
                    ccn[r] = csrow[c8 + 8 + r];
                }
            }
            #pragma unroll
            for (int r = 0; r < 8; r++) {
                float nb = fmaf(csy[r], vt, cmb[r]);   // vb' = s*vt + c*vb
                vt       = fmaf(csx[r], vt, -smb[r]);  // vt' = c*vt - s*vb
                bb[(c8 + r) * NP] = nb;
            }
        }
        M[it * NP + j] = vt;
    }
    __syncthreads();
    for (int i = 0; i < NP; i++)
        d_RT[j * NP + i] = M[i * NP + j] * mus[i];
}

// ---------------------------------------------------------------------------
// cp.async helpers
// ---------------------------------------------------------------------------
__device__ __forceinline__ void cpa16(void* smem, const void* g) {
    unsigned s = (unsigned)__cvta_generic_to_shared(smem);
    asm volatile("cp.async.cg.shared.global [%0], [%1], 16;\n" :: "r"(s), "l"(g));
}
__device__ __forceinline__ void cpa_commit() {
    asm volatile("cp.async.commit_group;\n");
}
template <int N>
__device__ __forceinline__ void cpa_wait() {
    asm volatile("cp.async.wait_group %0;\n" :: "n"(N));
}
__device__ __forceinline__ void fma2(u64& d, u64 a, u64 b) {
    asm("fma.rn.f32x2 %0, %1, %2, %0;" : "+l"(d) : "l"(a), "l"(b));
}
__device__ __forceinline__ u64 dup2(float v) {
    u64 r;
    asm("mov.b64 %0, {%1, %1};" : "=l"(r) : "r"(__float_as_uint(v)));
    return r;
}

// ---------------------------------------------------------------------------
// Kernel 2: Y = M @ X.  Block: 64 rows x 256 cols, 8 warps, 2 blocks/SM.
// X staged via cp.async in 8-row chunks through a 4-buffer ring, 2 chunks in
// flight, ONE __syncthreads per chunk. Thread: 8 rows x 8 cols.
// Per k: 2 LDS.128 (X) + 4 LDS.128 (R broadcast) -> 32 FFMA2.
// ---------------------------------------------------------------------------
__global__ void __launch_bounds__(256, 2)
gemm_kernel(const float* __restrict__ X, float* __restrict__ out) {
    __shared__ __align__(16) u64   sR[NP * NP];            // dup (v,v), 32 KB
    __shared__ __align__(16) float sX[NBUF][KCH * BCOLS];  // 4 x 8 KB

    const int tid = threadIdx.x;
    const float4* R4 = (const float4*)d_RT;
    for (int t = tid; t < NP * NP / 4; t += 256) {
        float4 v = R4[t];
        sR[t * 4 + 0] = dup2(v.x);
        sR[t * 4 + 1] = dup2(v.y);
        sR[t * 4 + 2] = dup2(v.z);
        sR[t * 4 + 3] = dup2(v.w);
    }

    const int lane = tid & 31;
    const int wid  = tid >> 5;
    const int col0 = blockIdx.x * BCOLS;

    // loader mapping: warp wid -> row wid of chunk; lane -> 8 floats (2x16B)
    const int gc0 = min(col0 + lane * 8 + 0, NCOLS - 4);
    const int gc1 = min(col0 + lane * 8 + 4, NCOLS - 4);
    float* const sbase = (float*)sX + wid * BCOLS + lane * 8;

    // prologue: chunks 0,1,2 -> buffers 0,1,2
    #pragma unroll
    for (int c = 0; c < 3; c++) {
        const size_t ro = (size_t)(c * KCH + wid) * NCOLS;
        float* d = sbase + c * (KCH * BCOLS);
        cpa16(d + 0, X + ro + gc0);
        cpa16(d + 4, X + ro + gc1);
        cpa_commit();
    }

    u64 aA[8][2], aB[8][2];
    #pragma unroll
    for (int il = 0; il < 8; il++) {
        aA[il][0] = aA[il][1] = 0ULL;
        aB[il][0] = aB[il][1] = 0ULL;
    }

    const int rbase = wid * 4;
    const ulonglong2* const sR2 = (const ulonglong2*)sR;

    #pragma unroll 1
    for (int ch = 0; ch < NCH; ch++) {
        cpa_wait<2>();          // chunk ch resident
        __syncthreads();        // also protects refill target (read last iter)

        const ulonglong2* xc = (const ulonglong2*)&sX[ch & (NBUF - 1)][0];
        #pragma unroll
        for (int k = 0; k < KCH; k++) {
            const ulonglong2 cA = xc[k * (BCOLS / 4) + lane];
            const ulonglong2 cB = xc[k * (BCOLS / 4) + lane + 32];
            ulonglong2 rv[4];
            #pragma unroll
            for (int u = 0; u < 4; u++)
                rv[u] = sR2[(ch * KCH + k) * 32 + rbase + u];
            #pragma unroll
            for (int il = 0; il < 8; il++) {
                const u64 Rd = (il & 1) ? rv[il >> 1].y : rv[il >> 1].x;
                fma2(aA[il][0], Rd, cA.x);
                fma2(aA[il][1], Rd, cA.y);
                fma2(aB[il][0], Rd, cB.x);
                fma2(aB[il][1], Rd, cB.y);
            }
        }

        if (ch + 3 < NCH) {     // refill buffer (ch+3)%4 == (ch-1)%4
            const size_t ro = (size_t)((ch + 3) * KCH + wid) * NCOLS;
            float* d = sbase + ((ch + 3) & (NBUF - 1)) * (KCH * BCOLS);
            cpa16(d + 0, X + ro + gc0);
            cpa16(d + 4, X + ro + gc1);
        }
        cpa_commit();           // empty commits keep group arithmetic aligned
    }

    const int colA = col0 + lane * 4;
    const int colB = colA + 128;
    #pragma unroll
    for (int il = 0; il < 8; il++) {
        const int i = wid * 8 + il;
        if (colA < NCOLS) {
            ulonglong2 v; v.x = aA[il][0]; v.y = aA[il][1];
            *(ulonglong2*)(out + (size_t)i * NCOLS + colA) = v;
        }
        if (colB < NCOLS) {
            ulonglong2 v; v.x = aB[il][0]; v.y = aB[il][1];
            *(ulonglong2*)(out + (size_t)i * NCOLS + colB) = v;
        }
    }
}

// ---------------------------------------------------------------------------
extern "C" void kernel_launch(void* const* d_in, const int* in_sizes, int n_in,
                              void* d_out, int out_size) {
    const float* X      = (const float*)d_in[0];
    const float* angles = (const float*)d_in[1];
    const float* mus    = (const float*)d_in[2];
    float*       out    = (float*)d_out;

    build_R_kernel<<<1, NP>>>(angles, mus);
    gemm_kernel<<<NB, 256>>>(X, out);
}

// round 7
// speedup vs baseline: 1.0397x; 1.0397x over previous
#include <cuda_runtime.h>

typedef unsigned long long u64;

#define NP 64
#define NCOLS 500000
#define BCOLS 256
#define NB    ((NCOLS + BCOLS - 1) / BCOLS)   /* 1954 gemm blocks */
#define NANG 2016
#define KCH   8                               /* K rows per staged chunk */
#define NCH   (NP / KCH)                      /* 8 chunks */
#define NBUF  4                               /* smem ring depth */

// RT[r*64 + i] = mus[i] * R[i][r]
__device__ float d_RT[NP * NP];
__device__ int   d_flag = 0;   // R-ready flag (reset by last block each launch)
__device__ int   d_done = 0;   // blocks-past-spin counter

// ---------------------------------------------------------------------------
// helpers
// ---------------------------------------------------------------------------
__device__ __forceinline__ void cpa16(void* smem, const void* g) {
    unsigned s = (unsigned)__cvta_generic_to_shared(smem);
    asm volatile("cp.async.cg.shared.global [%0], [%1], 16;\n" :: "r"(s), "l"(g));
}
__device__ __forceinline__ void cpa_commit() {
    asm volatile("cp.async.commit_group;\n");
}
template <int N>
__device__ __forceinline__ void cpa_wait() {
    asm volatile("cp.async.wait_group %0;\n" :: "n"(N));
}
__device__ __forceinline__ void fma2(u64& d, u64 a, u64 b) {
    asm("fma.rn.f32x2 %0, %1, %2, %0;" : "+l"(d) : "l"(a), "l"(b));
}
__device__ __forceinline__ u64 dup2(float v) {
    u64 r;
    asm("mov.b64 %0, {%1, %1};" : "=l"(r) : "r"(__float_as_uint(v)));
    return r;
}

// ---------------------------------------------------------------------------
// Fused kernel.
// Block 0: build the 64x64 combined rotation matrix, publish via d_flag.
// Blocks 1..NB: prefetch X (independent of R), spin on d_flag, then GEMM.
// ---------------------------------------------------------------------------
__global__ void __launch_bounds__(256, 2)
fused_kernel(const float* __restrict__ X,
             const float* __restrict__ angles,
             const float* __restrict__ mus,
             float* __restrict__ out) {
    __shared__ __align__(16) u64   sR[NP * NP];            // 32 KB
    __shared__ __align__(16) float sX[NBUF][KCH * BCOLS];  // 32 KB

    const int tid = threadIdx.x;

    // =======================================================================
    // Block 0: build R (threads 0..63; smem aliased onto sR/sX).
    // Distance-2 mb prefetch, vt carried in a register: 1-FFMA chain/rotation.
    // =======================================================================
    if (blockIdx.x == 0) {
        float2* cs = (float2*)sR;            // (NANG+2)*8B = 16.1 KB <= 32 KB
        float*  M  = (float*)sX;             // (NP+2)*NP*4B = 16.9 KB <= 32 KB
        const int j = tid;

        if (j < NP) {
            for (int k = j; k < NANG; k += NP) {
                float s, c;
                sincosf(angles[k], &s, &c);
                cs[k] = make_float2(c, s);
            }
            if (j < 2) cs[NANG + j] = make_float2(0.f, 0.f);
            #pragma unroll
            for (int i = 0; i < NP + 2; i++) M[i * NP + j] = (i == j) ? 1.0f : 0.0f;
        }
        __syncthreads();

        if (j < NP) {
            float* col = &M[j];
            int k = 0;
            for (int it = 0; it < NP - 1; it++) {
                float vt     = col[it * NP];
                float mb     = col[(it + 1) * NP];
                float2 csc   = cs[k];
                float smb    = csc.y * mb;
                float cmb    = csc.x * mb;
                float mb_nxt = col[(it + 2) * NP];
                const int n  = NP - 1 - it;
                for (int r = 0; r < n; r++) {
                    float  mb2 = col[(it + 3 + r) * NP];   // dist-2 prefetch (pad-safe)
                    float2 csn = cs[k + r + 1];            // pad-safe
                    float  nb  = fmaf(csc.y, vt, cmb);     // vb' = s*vt + c*vb
                    vt         = fmaf(csc.x, vt, -smb);    // vt' = c*vt - s*vb
                    col[(it + 1 + r) * NP] = nb;
                    smb = csn.y * mb_nxt;
                    cmb = csn.x * mb_nxt;
                    mb_nxt = mb2;
                    csc = csn;
                }
                col[it * NP] = vt;
                k += n;
            }
        }
        __syncthreads();
        if (j < NP) {
            for (int i = 0; i < NP; i++)
                d_RT[j * NP + i] = M[i * NP + j] * mus[i];
        }
        __syncthreads();
        if (tid == 0) {
            __threadfence();                 // release
            atomicExch(&d_flag, 1);
        }
        return;
    }

    // =======================================================================
    // GEMM blocks
    // =======================================================================
    const int lane = tid & 31;
    const int wid  = tid >> 5;
    const int col0 = (blockIdx.x - 1) * BCOLS;

    // loader mapping: warp wid -> row wid of chunk; lane -> 8 floats (2x16B)
    const int gc0 = min(col0 + lane * 8 + 0, NCOLS - 4);
    const int gc1 = min(col0 + lane * 8 + 4, NCOLS - 4);
    float* const sbase = (float*)sX + wid * BCOLS + lane * 8;

    // prologue: chunks 0,1,2 -> buffers 0,1,2  (independent of R)
    #pragma unroll
    for (int c = 0; c < 3; c++) {
        const size_t ro = (size_t)(c * KCH + wid) * NCOLS;
        float* d = sbase + c * (KCH * BCOLS);
        cpa16(d + 0, X + ro + gc0);
        cpa16(d + 4, X + ro + gc1);
        cpa_commit();
    }

    // wait for R (overlaps with the DRAM prologue above)
    if (tid == 0) {
        while (atomicAdd(&d_flag, 0) == 0) __nanosleep(128);
        __threadfence();                     // acquire
        if (atomicAdd(&d_done, 1) == NB - 1) {   // last block past the spin:
            d_done = 0;                          // restore launch invariants
            d_flag = 0;
        }
    }
    __syncthreads();

    // stage R into smem as duplicated (v,v) u64 pairs
    const float4* R4 = (const float4*)d_RT;
    for (int t = tid; t < NP * NP / 4; t += 256) {
        float4 v = R4[t];
        sR[t * 4 + 0] = dup2(v.x);
        sR[t * 4 + 1] = dup2(v.y);
        sR[t * 4 + 2] = dup2(v.z);
        sR[t * 4 + 3] = dup2(v.w);
    }

    u64 aA[8][2], aB[8][2];
    #pragma unroll
    for (int il = 0; il < 8; il++) {
        aA[il][0] = aA[il][1] = 0ULL;
        aB[il][0] = aB[il][1] = 0ULL;
    }

    const int rbase = wid * 4;
    const ulonglong2* const sR2 = (const ulonglong2*)sR;

    #pragma unroll 1
    for (int ch = 0; ch < NCH; ch++) {
        cpa_wait<2>();          // chunk ch resident
        __syncthreads();        // also protects refill target + sR visibility

        const ulonglong2* xc = (const ulonglong2*)&sX[ch & (NBUF - 1)][0];
        #pragma unroll
        for (int k = 0; k < KCH; k++) {
            const ulonglong2 cA = xc[k * (BCOLS / 4) + lane];
            const ulonglong2 cB = xc[k * (BCOLS / 4) + lane + 32];
            ulonglong2 rv[4];
            #pragma unroll
            for (int u = 0; u < 4; u++)
                rv[u] = sR2[(ch * KCH + k) * 32 + rbase + u];
            #pragma unroll
            for (int il = 0; il < 8; il++) {
                const u64 Rd = (il & 1) ? rv[il >> 1].y : rv[il >> 1].x;
                fma2(aA[il][0], Rd, cA.x);
                fma2(aA[il][1], Rd, cA.y);
                fma2(aB[il][0], Rd, cB.x);
                fma2(aB[il][1], Rd, cB.y);
            }
        }

        if (ch + 3 < NCH) {     // refill buffer (ch+3)%4
            const size_t ro = (size_t)((ch + 3) * KCH + wid) * NCOLS;
            float* d = sbase + ((ch + 3) & (NBUF - 1)) * (KCH * BCOLS);
            cpa16(d + 0, X + ro + gc0);
            cpa16(d + 4, X + ro + gc1);
        }
        cpa_commit();           // keep group counts aligned
    }

    const int colA = col0 + lane * 4;
    const int colB = colA + 128;
    #pragma unroll
    for (int il = 0; il < 8; il++) {
        const int i = wid * 8 + il;
        if (colA < NCOLS) {
            ulonglong2 v; v.x = aA[il][0]; v.y = aA[il][1];
            *(ulonglong2*)(out + (size_t)i * NCOLS + colA) = v;
        }
        if (colB < NCOLS) {
            ulonglong2 v; v.x = aB[il][0]; v.y = aB[il][1];
            *(ulonglong2*)(out + (size_t)i * NCOLS + colB) = v;
        }
    }
}

// ---------------------------------------------------------------------------
extern "C" void kernel_launch(void* const* d_in, const int* in_sizes, int n_in,
                              void* d_out, int out_size) {
    const float* X      = (const float*)d_in[0];
    const float* angles = (const float*)d_in[1];
    const float* mus    = (const float*)d_in[2];
    float*       out    = (float*)d_out;

    fused_kernel<<<NB + 1, 256>>>(X, angles, mus, out);
}